// round 2
// baseline (speedup 1.0000x reference)
#include <cuda_runtime.h>
#include <math.h>

#define NBATCH 2048

// shared-memory layout (float offsets)
#define S_IM    8                    // 3*64 rows, stride 66 = 12672 floats (8 floats slack in front for ix<0 guarded loads)
#define S_W1    (S_IM + 12672)       // conv1 weights transposed: [c][ky][f][12] = 3*11*10*12 = 3960
#define S_C1    (S_W1 + 3960)       // conv1 out: [10][15][16] = 2400
#define S_W2    (S_C1 + 2400)       // conv2 weights: [16][10][5][5] = 4000
#define S_P1    (S_W2 + 4000)       // pool1 out: [10][7][8] = 560
#define S_C2    (S_P1 + 560)        // conv2 out: [16][4][4] = 256
#define S_FL    (S_C2 + 256)        // flat: 64
#define SMEM_FLOATS (S_FL + 64)     // 23920 floats = 95680 bytes

__device__ __forceinline__ float leaky(float v) { return v > 0.f ? v : 0.01f * v; }

__global__ void __launch_bounds__(256, 2)
cnn_kernel(const float* __restrict__ im,
           const float* __restrict__ w1,
           const float* __restrict__ w2,
           const float* __restrict__ b2,
           const float* __restrict__ lw,
           const float* __restrict__ lb,
           float* __restrict__ out)
{
    extern __shared__ float sm[];
    const int b   = blockIdx.x;
    const int tid = threadIdx.x;

    // ---- stage image (12288 floats) as float2 into padded rows (stride 66) ----
    {
        const float2* gim = (const float2*)(im + (size_t)b * 12288);
        for (int i = tid; i < 6144; i += 256) {
            float2 v = gim[i];
            int fi  = i << 1;          // float index within [c][64][64]
            int row = fi >> 6;         // c*64 + y, 0..191
            int col = fi & 63;
            sm[S_IM + row * 66 + col]     = v.x;
            sm[S_IM + row * 66 + col + 1] = v.y;
        }
    }
    // ---- stage conv1 weights transposed: [f][c][ky][kx] -> [c][ky][f][12] ----
    for (int i = tid; i < 3630; i += 256) {
        int kx = i % 11; int t = i / 11;
        int ky = t % 11; t /= 11;
        int c  = t % 3;  int f = t / 3;
        sm[S_W1 + ((c * 11 + ky) * 10 + f) * 12 + kx] = w1[i];
    }
    for (int i = tid; i < 330; i += 256)       // zero the kx=11 pad lane
        sm[S_W1 + i * 12 + 11] = 0.f;
    // ---- stage conv2 weights ----
    for (int i = tid; i < 4000; i += 256)
        sm[S_W2 + i] = w2[i];

    // softmax of identical logits over 20 nodes == exactly 0.05 (see R0 analysis;
    // confirmed: output 0 rel_err == 0.0 in R1 bench)
    if (tid < 20)
        out[b * 20 + tid] = 0.05f;

    __syncthreads();

    // ---- conv1 (11x11, stride 4, pad 2): 15x15 spatial, 10 filters ----
    if (tid < 225) {
        const int oy = tid / 15, ox = tid % 15;
        const int ix0 = ox * 4 - 2;
        const int iy0 = oy * 4 - 2;
        float acc[10];
        #pragma unroll
        for (int f = 0; f < 10; f++) acc[f] = 0.f;

        for (int c = 0; c < 3; c++) {
            #pragma unroll
            for (int ky = 0; ky < 11; ky++) {
                int iy = iy0 + ky;
                if ((unsigned)iy < 64u) {
                    const float* irow = &sm[S_IM + (c * 64 + iy) * 66];
                    float in[11];
                    #pragma unroll
                    for (int k = 0; k < 11; k++) {
                        int ix = ix0 + k;
                        in[k] = ((unsigned)ix < 64u) ? irow[ix] : 0.f;
                    }
                    const float4* wrow = (const float4*)&sm[S_W1 + ((c * 11 + ky) * 10) * 12];
                    #pragma unroll
                    for (int f = 0; f < 10; f++) {
                        float4 wa = wrow[f * 3 + 0];
                        float4 wb = wrow[f * 3 + 1];
                        float4 wc = wrow[f * 3 + 2];
                        float a = acc[f];
                        a = fmaf(in[0], wa.x, a); a = fmaf(in[1], wa.y, a);
                        a = fmaf(in[2], wa.z, a); a = fmaf(in[3], wa.w, a);
                        a = fmaf(in[4], wb.x, a); a = fmaf(in[5], wb.y, a);
                        a = fmaf(in[6], wb.z, a); a = fmaf(in[7], wb.w, a);
                        a = fmaf(in[8], wc.x, a); a = fmaf(in[9], wc.y, a);
                        a = fmaf(in[10], wc.z, a);
                        acc[f] = a;
                    }
                }
            }
        }
        #pragma unroll
        for (int f = 0; f < 10; f++)
            sm[S_C1 + (f * 15 + oy) * 16 + ox] = leaky(acc[f]);
    }
    __syncthreads();

    // ---- maxpool 3x3 stride 2: 15x15 -> 7x7, 10 channels (490 outputs) ----
    // R1 BUG FIX: 490 > blockDim (256); must be a strided loop, not `if (tid < 490)`.
    for (int i = tid; i < 490; i += 256) {
        int f = i / 49, r = i % 49;
        int py = r / 7, px = r % 7;
        float m = -1e30f;
        #pragma unroll
        for (int dy = 0; dy < 3; dy++)
            #pragma unroll
            for (int dx = 0; dx < 3; dx++) {
                float v = sm[S_C1 + (f * 15 + (2 * py + dy)) * 16 + (2 * px + dx)];
                m = fmaxf(m, v);
            }
        sm[S_P1 + (f * 7 + py) * 8 + px] = m;
    }
    __syncthreads();

    // ---- conv2 (5x5, stride 2, pad 2): 7x7 -> 4x4, 10 -> 16 channels ----
    {
        int f   = tid >> 4;
        int r   = tid & 15;
        int oy2 = r >> 2;
        int ox2 = r & 3;
        float a = b2[f];
        for (int c = 0; c < 10; c++) {
            #pragma unroll
            for (int ky = 0; ky < 5; ky++) {
                int iy = 2 * oy2 - 2 + ky;
                if ((unsigned)iy < 7u) {
                    #pragma unroll
                    for (int kx = 0; kx < 5; kx++) {
                        int ix = 2 * ox2 - 2 + kx;
                        if ((unsigned)ix < 7u)
                            a = fmaf(sm[S_P1 + (c * 7 + iy) * 8 + ix],
                                     sm[S_W2 + ((f * 10 + c) * 5 + ky) * 5 + kx], a);
                    }
                }
            }
        }
        sm[S_C2 + f * 16 + oy2 * 4 + ox2] = leaky(a);
    }
    __syncthreads();

    // ---- maxpool 2x2 stride 2: 4x4 -> 2x2, flatten to 64 ----
    if (tid < 64) {
        int f = tid >> 2, py = (tid >> 1) & 1, px = tid & 1;
        float m = sm[S_C2 + f * 16 + (2 * py) * 4 + (2 * px)];
        m = fmaxf(m, sm[S_C2 + f * 16 + (2 * py) * 4 + (2 * px + 1)]);
        m = fmaxf(m, sm[S_C2 + f * 16 + (2 * py + 1) * 4 + (2 * px)]);
        m = fmaxf(m, sm[S_C2 + f * 16 + (2 * py + 1) * 4 + (2 * px + 1)]);
        sm[S_FL + tid] = m;   // flat index = f*4 + py*2 + px == tid ✓
    }
    __syncthreads();

    // ---- linear 64 -> 2 + sigmoid -> img_feat ----
    if (tid < 2) {
        float a = lb[tid];
        #pragma unroll
        for (int k = 0; k < 64; k++)
            a = fmaf(sm[S_FL + k], lw[tid * 64 + k], a);
        float s = 1.f / (1.f + __expf(-a));
        out[NBATCH * 20 + b * 2 + tid] = s;
    }
}

extern "C" void kernel_launch(void* const* d_in, const int* in_sizes, int n_in,
                              void* d_out, int out_size)
{
    (void)in_sizes; (void)n_in; (void)out_size;
    const float* im = (const float*)d_in[0];
    // d_in[1] = x, d_in[2] = edge_index : dead (softmax of graph-constant logits == 0.05)
    const float* w1 = (const float*)d_in[3];
    const float* w2 = (const float*)d_in[4];
    const float* b2 = (const float*)d_in[5];
    const float* lw = (const float*)d_in[6];
    const float* lb = (const float*)d_in[7];
    float* out = (float*)d_out;

    cudaFuncSetAttribute(cnn_kernel, cudaFuncAttributeMaxDynamicSharedMemorySize,
                         SMEM_FLOATS * sizeof(float));
    cnn_kernel<<<NBATCH, 256, SMEM_FLOATS * sizeof(float)>>>(im, w1, w2, b2, lw, lb, out);
}

// round 3
// speedup vs baseline: 1.1522x; 1.1522x over previous
#include <cuda_runtime.h>
#include <math.h>

#define NBATCH 2048

// ---- shared memory layout (float offsets) ----
// Image region (reused after conv1):
//   phase-split padded image: 3 ch x 67 rows x 68 slots = 13668 floats
//   slot(x) = ((x+2)&3)*17 + ((x+2)>>2), row ry = y+2 (rows 0,1,66 = zero halo)
#define IMROW 68
#define IMCH  (67 * IMROW)          // 4556
#define S_IM  0
#define S_W1  13668                 // conv1 weights transposed [c][ky][f][12] = 3960
#define SMEM_FLOATS (S_W1 + 3960)   // 17628 floats = 70512 bytes  -> 3 CTAs/SM

// aliases inside the (dead after conv1) image region:
#define S_C1  0                     // conv1 out [10][15][16] = 2400
#define S_W2  2432                  // conv2 weights = 4000
#define S_P1  6432                  // pool1 out [10][7][8] = 560
#define S_C2  6992                  // conv2 out [16][4][4] = 256
#define S_FL  7248                  // flat 64

__device__ __forceinline__ float leaky(float v) { return v > 0.f ? v : 0.01f * v; }

__global__ void __launch_bounds__(256, 3)
cnn_kernel(const float* __restrict__ im,
           const float* __restrict__ w1,
           const float* __restrict__ w2,
           const float* __restrict__ b2,
           const float* __restrict__ lw,
           const float* __restrict__ lb,
           float* __restrict__ out)
{
    extern __shared__ float sm[];
    const int b   = blockIdx.x;
    const int tid = threadIdx.x;

    // ---- stage image into phase-split, zero-padded layout ----
    {
        const float2* gim = (const float2*)(im + (size_t)b * 12288);
        for (int i = tid; i < 6144; i += 256) {
            float2 v = gim[i];
            int fi = i << 1;
            int c  = fi >> 12;
            int y  = (fi & 4095) >> 6;
            int x  = fi & 63;
            int base = c * IMCH + (y + 2) * IMROW;
            int xp = x + 2;
            sm[base + (xp & 3) * 17 + (xp >> 2)] = v.x;
            xp++;
            sm[base + (xp & 3) * 17 + (xp >> 2)] = v.y;
        }
        // zero halo rows ry in {0,1,66}: 3ch * 3rows * 68 = 612
        for (int i = tid; i < 612; i += 256) {
            int c = i / 204, r = i % 204;
            int ry = r / 68; ry = (ry == 2) ? 66 : ry;
            sm[c * IMCH + ry * IMROW + (r % 68)] = 0.f;
        }
        // zero halo columns (slots 0,17,50,67) in valid rows: 3ch*64rows*4 = 768
        for (int i = tid; i < 768; i += 256) {
            int c = i >> 8, r = i & 255;
            int ry = (r >> 2) + 2;
            int s4 = r & 3;
            int slot = (s4 == 0) ? 0 : (s4 == 1) ? 17 : (s4 == 2) ? 50 : 67;
            sm[c * IMCH + ry * IMROW + slot] = 0.f;
        }
    }
    // ---- stage conv1 weights transposed: [f][c][ky][kx] -> [c][ky][f][12] ----
    for (int i = tid; i < 3630; i += 256) {
        int kx = i % 11; int t = i / 11;
        int ky = t % 11; t /= 11;
        int c  = t % 3;  int f = t / 3;
        sm[S_W1 + ((c * 11 + ky) * 10 + f) * 12 + kx] = w1[i];
    }

    // softmax of graph-constant logits over 20 nodes == exactly 0.05 (verified R1/R2)
    if (tid < 20)
        out[b * 20 + tid] = 0.05f;

    __syncthreads();

    // ---- conv1 (11x11, stride 4, pad 2): 15x15 out, 10 filters ----
    // thread map: oy = tid>>4 (0..14), ox = tid&15 (active ox<15)
    // guard-free: halo is zero-filled; loads conflict-free (phase-split layout)
    const int oy = tid >> 4, ox = tid & 15;
    const bool c1act = (tid < 240) && (ox < 15);
    float acc[10];
    #pragma unroll
    for (int f = 0; f < 10; f++) acc[f] = 0.f;

    if (c1act) {
        #pragma unroll 1
        for (int c = 0; c < 3; c++) {
            #pragma unroll
            for (int ky = 0; ky < 11; ky++) {
                // row ry = (4*oy - 2 + ky) + 2 = 4*oy + ky  (always in [0,66])
                const float* irow = &sm[c * IMCH + (4 * oy + ky) * IMROW + ox];
                float in[11];
                #pragma unroll
                for (int k = 0; k < 11; k++)
                    in[k] = irow[(k & 3) * 17 + (k >> 2)];
                const float4* wrow = (const float4*)&sm[S_W1 + ((c * 11 + ky) * 10) * 12];
                #pragma unroll
                for (int f = 0; f < 10; f++) {
                    float4 wa = wrow[f * 3 + 0];
                    float4 wb = wrow[f * 3 + 1];
                    float4 wc = wrow[f * 3 + 2];
                    float a = acc[f];
                    a = fmaf(in[0], wa.x, a); a = fmaf(in[1], wa.y, a);
                    a = fmaf(in[2], wa.z, a); a = fmaf(in[3], wa.w, a);
                    a = fmaf(in[4], wb.x, a); a = fmaf(in[5], wb.y, a);
                    a = fmaf(in[6], wb.z, a); a = fmaf(in[7], wb.w, a);
                    a = fmaf(in[8], wc.x, a); a = fmaf(in[9], wc.y, a);
                    a = fmaf(in[10], wc.z, a);
                    acc[f] = a;
                }
            }
        }
    }
    __syncthreads();   // all image reads done; image region now reusable

    if (c1act) {
        #pragma unroll
        for (int f = 0; f < 10; f++)
            sm[S_C1 + (f * 15 + oy) * 16 + ox] = leaky(acc[f]);
    }
    // stage conv2 weights into the freed image region
    for (int i = tid; i < 4000; i += 256)
        sm[S_W2 + i] = w2[i];
    __syncthreads();

    // ---- maxpool 3x3 stride 2: 15x15 -> 7x7, 10 channels (490 outputs) ----
    for (int i = tid; i < 490; i += 256) {
        int f = i / 49, r = i % 49;
        int py = r / 7, px = r % 7;
        float m = -1e30f;
        #pragma unroll
        for (int dy = 0; dy < 3; dy++)
            #pragma unroll
            for (int dx = 0; dx < 3; dx++)
                m = fmaxf(m, sm[S_C1 + (f * 15 + (2 * py + dy)) * 16 + (2 * px + dx)]);
        sm[S_P1 + (f * 7 + py) * 8 + px] = m;
    }
    __syncthreads();

    // ---- conv2 (5x5, stride 2, pad 2): 7x7 -> 4x4, 10 -> 16 channels ----
    {
        int f   = tid >> 4;
        int r   = tid & 15;
        int oy2 = r >> 2;
        int ox2 = r & 3;
        float a = b2[f];
        for (int c = 0; c < 10; c++) {
            #pragma unroll
            for (int ky = 0; ky < 5; ky++) {
                int iy = 2 * oy2 - 2 + ky;
                if ((unsigned)iy < 7u) {
                    #pragma unroll
                    for (int kx = 0; kx < 5; kx++) {
                        int ix = 2 * ox2 - 2 + kx;
                        if ((unsigned)ix < 7u)
                            a = fmaf(sm[S_P1 + (c * 7 + iy) * 8 + ix],
                                     sm[S_W2 + ((f * 10 + c) * 5 + ky) * 5 + kx], a);
                    }
                }
            }
        }
        sm[S_C2 + f * 16 + oy2 * 4 + ox2] = leaky(a);
    }
    __syncthreads();

    // ---- maxpool 2x2 stride 2: 4x4 -> 2x2, flatten to 64 ----
    if (tid < 64) {
        int f = tid >> 2, py = (tid >> 1) & 1, px = tid & 1;
        float m = sm[S_C2 + f * 16 + (2 * py) * 4 + (2 * px)];
        m = fmaxf(m, sm[S_C2 + f * 16 + (2 * py) * 4 + (2 * px + 1)]);
        m = fmaxf(m, sm[S_C2 + f * 16 + (2 * py + 1) * 4 + (2 * px)]);
        m = fmaxf(m, sm[S_C2 + f * 16 + (2 * py + 1) * 4 + (2 * px + 1)]);
        sm[S_FL + tid] = m;   // flat index = f*4 + py*2 + px == tid
    }
    __syncthreads();

    // ---- linear 64 -> 2 + sigmoid -> img_feat ----
    if (tid < 2) {
        float a = lb[tid];
        #pragma unroll
        for (int k = 0; k < 64; k++)
            a = fmaf(sm[S_FL + k], lw[tid * 64 + k], a);
        out[NBATCH * 20 + b * 2 + tid] = 1.f / (1.f + __expf(-a));
    }
}

extern "C" void kernel_launch(void* const* d_in, const int* in_sizes, int n_in,
                              void* d_out, int out_size)
{
    (void)in_sizes; (void)n_in; (void)out_size;
    const float* im = (const float*)d_in[0];
    // d_in[1] = x, d_in[2] = edge_index : dead (softmax of graph-constant logits == 0.05)
    const float* w1 = (const float*)d_in[3];
    const float* w2 = (const float*)d_in[4];
    const float* b2 = (const float*)d_in[5];
    const float* lw = (const float*)d_in[6];
    const float* lb = (const float*)d_in[7];
    float* out = (float*)d_out;

    cudaFuncSetAttribute(cnn_kernel, cudaFuncAttributeMaxDynamicSharedMemorySize,
                         SMEM_FLOATS * sizeof(float));
    cnn_kernel<<<NBATCH, 256, SMEM_FLOATS * sizeof(float)>>>(im, w1, w2, b2, lw, lb, out);
}

// round 4
// speedup vs baseline: 1.5219x; 1.3209x over previous
#include <cuda_runtime.h>
#include <math.h>

#define NBATCH 2048

// ---- image layout: phase-split, zero halo, conflict-free ----
// row ry = y+2 (0..66), phase ph = xp&3, slot = ph*18 + (xp>>2), xp = x+2 (0..67)
#define IMROW 74                    // 4*74 = 296 ≡ 8 mod 32 -> oy groups hit banks {0,8,16,24}
#define IMCH  (67 * IMROW)          // 4958
#define S_W1  14876                 // conv1 weights [c][ky][f][12] = 3960 (float4-aligned base)
#define SMEM_FLOATS (S_W1 + 3960)   // 18836 floats = 75344 bytes -> 3 CTAs/SM

// aliases in the image region (dead after conv1):
#define S_C1   0                    // conv1 out [10][15][16] = 2400
#define S_W2P  2400                 // conv2 weights padded [16][10][5][8] = 6400
#define S_P1P  8800                 // pool1 out zero-padded [10][11][12] = 1320
#define S_C2   10120                // conv2 out [16][4][4] = 256
#define S_FL   10376                // flat 64

__device__ __forceinline__ float leaky(float v) { return v > 0.f ? v : 0.01f * v; }

__global__ void __launch_bounds__(256, 3)
cnn_kernel(const float* __restrict__ im,
           const float* __restrict__ w1,
           const float* __restrict__ w2,
           const float* __restrict__ b2,
           const float* __restrict__ lw,
           const float* __restrict__ lb,
           float* __restrict__ out)
{
    extern __shared__ float sm[];
    const int b   = blockIdx.x;
    const int tid = threadIdx.x;

    // ---- zero whole image region (halo correctness), then sync, then scatter ----
    for (int i = tid; i < 3 * IMCH; i += 256) sm[i] = 0.f;
    __syncthreads();

    {
        const float2* gim = (const float2*)(im + (size_t)b * 12288);
        for (int i = tid; i < 6144; i += 256) {
            float2 v = gim[i];
            int fi = i << 1;
            int c  = fi >> 12;
            int y  = (fi & 4095) >> 6;
            int x  = fi & 63;
            int base = c * IMCH + (y + 2) * IMROW;
            int xp = x + 2;
            sm[base + (xp & 3) * 18 + (xp >> 2)] = v.x;
            xp++;
            sm[base + (xp & 3) * 18 + (xp >> 2)] = v.y;
        }
    }
    // conv1 weights transposed: [f][c][ky][kx] -> [c][ky][f][12] (pad lane unused)
    for (int i = tid; i < 3630; i += 256) {
        int kx = i % 11; int t = i / 11;
        int ky = t % 11; t /= 11;
        int c  = t % 3;  int f = t / 3;
        sm[S_W1 + ((c * 11 + ky) * 10 + f) * 12 + kx] = w1[i];
    }

    // graph half is analytically constant: softmax == 0.05 (verified exact R1-R3)
    if (tid < 20)
        out[b * 20 + tid] = 0.05f;

    __syncthreads();

    // ---- conv1 (11x11, s4, p2): 15x15 out, 10 filters, 2 pixels/thread ----
    // thread t<120: oy = t>>3 (0..14), pr = t&7; pixels (oy,pr) and (oy,pr+8)
    const int oy = tid >> 3, pr = tid & 7;
    const bool c1act = (tid < 120);
    float acc1[10], acc2[10];
    #pragma unroll
    for (int f = 0; f < 10; f++) { acc1[f] = 0.f; acc2[f] = 0.f; }

    if (c1act) {
        #pragma unroll 1
        for (int c = 0; c < 3; c++) {
            const float*  ip0 = &sm[c * IMCH + (4 * oy) * IMROW + pr];
            const float4* wp0 = (const float4*)&sm[S_W1 + (c * 11 * 10) * 12];
            #pragma unroll 1
            for (int ky = 0; ky < 11; ky++) {
                const float* ip = ip0 + ky * IMROW;
                // pixel1 inputs: k = ph + 4*j  (slot = ph*18 + pr + j)
                float a0 = ip[0],  a1 = ip[1],  a2 = ip[2];    // ph0: k=0,4,8
                float b0 = ip[18], b1 = ip[19], b2v = ip[20];  // ph1: k=1,5,9
                float c0 = ip[36], c1 = ip[37], c2 = ip[38];   // ph2: k=2,6,10
                float d0 = ip[54], d1 = ip[55];                // ph3: k=3,7
                // pixel2 (col pr+8): same k, slot +8
                float A0 = ip[8],  A1 = ip[9],  A2 = ip[10];
                float B0 = ip[26], B1 = ip[27], B2 = ip[28];
                float C0 = ip[44], C1 = ip[45], C2 = ip[46];
                float D0 = ip[62], D1 = ip[63];

                const float4* wrow = wp0 + ky * 30;
                #pragma unroll
                for (int f = 0; f < 10; f++) {
                    float4 wa = wrow[f * 3 + 0];   // w0..w3
                    float4 wb = wrow[f * 3 + 1];   // w4..w7
                    float4 wc = wrow[f * 3 + 2];   // w8..w10 (+pad)
                    float s = acc1[f];
                    s = fmaf(a0, wa.x, s); s = fmaf(b0, wa.y, s);
                    s = fmaf(c0, wa.z, s); s = fmaf(d0, wa.w, s);
                    s = fmaf(a1, wb.x, s); s = fmaf(b1, wb.y, s);
                    s = fmaf(c1, wb.z, s); s = fmaf(d1, wb.w, s);
                    s = fmaf(a2, wc.x, s); s = fmaf(b2v, wc.y, s);
                    s = fmaf(c2, wc.z, s);
                    acc1[f] = s;
                    float q = acc2[f];
                    q = fmaf(A0, wa.x, q); q = fmaf(B0, wa.y, q);
                    q = fmaf(C0, wa.z, q); q = fmaf(D0, wa.w, q);
                    q = fmaf(A1, wb.x, q); q = fmaf(B1, wb.y, q);
                    q = fmaf(C1, wb.z, q); q = fmaf(D1, wb.w, q);
                    q = fmaf(A2, wc.x, q); q = fmaf(B2, wc.y, q);
                    q = fmaf(C2, wc.z, q);
                    acc2[f] = q;
                }
            }
        }
    }
    __syncthreads();   // image reads done; region reusable

    if (c1act) {
        #pragma unroll
        for (int f = 0; f < 10; f++) {
            sm[S_C1 + (f * 15 + oy) * 16 + pr] = leaky(acc1[f]);
            if (pr < 7)
                sm[S_C1 + (f * 15 + oy) * 16 + pr + 8] = leaky(acc2[f]);
        }
    }
    // stage conv2 weights padded [f][c][ky][8]
    for (int i = tid; i < 4000; i += 256) {
        int kx = i % 5; int t = i / 5;
        int ky = t % 5; t /= 5;
        int c  = t % 10; int f = t / 10;
        sm[S_W2P + (((f * 10 + c) * 5) + ky) * 8 + kx] = w2[i];
    }
    // zero-fill padded pool1 buffer
    for (int i = tid; i < 1320; i += 256)
        sm[S_P1P + i] = 0.f;
    __syncthreads();

    // ---- maxpool 3x3 s2: 15x15 -> 7x7, write into zero-padded [10][11][12] ----
    for (int i = tid; i < 490; i += 256) {
        int f = i / 49, r = i % 49;
        int py = r / 7, px = r % 7;
        float m = -1e30f;
        #pragma unroll
        for (int dy = 0; dy < 3; dy++)
            #pragma unroll
            for (int dx = 0; dx < 3; dx++)
                m = fmaxf(m, sm[S_C1 + (f * 15 + (2 * py + dy)) * 16 + (2 * px + dx)]);
        sm[S_P1P + (f * 11 + py + 2) * 12 + px + 2] = m;
    }
    __syncthreads();

    // ---- conv2 (5x5, s2, p2): 7x7 -> 4x4, 10 -> 16 ch, guard-free ----
    {
        int f   = tid >> 4;
        int r   = tid & 15;
        int oy2 = r >> 2;
        int ox2 = r & 3;
        float a = b2[f];
        #pragma unroll 1
        for (int c = 0; c < 10; c++) {
            #pragma unroll
            for (int ky = 0; ky < 5; ky++) {
                const float* prow = &sm[S_P1P + (c * 11 + 2 * oy2 + ky) * 12 + 2 * ox2];
                const float4 wv = *(const float4*)&sm[S_W2P + ((f * 10 + c) * 5 + ky) * 8];
                const float  w4 = sm[S_W2P + ((f * 10 + c) * 5 + ky) * 8 + 4];
                a = fmaf(prow[0], wv.x, a);
                a = fmaf(prow[1], wv.y, a);
                a = fmaf(prow[2], wv.z, a);
                a = fmaf(prow[3], wv.w, a);
                a = fmaf(prow[4], w4,  a);
            }
        }
        sm[S_C2 + f * 16 + oy2 * 4 + ox2] = leaky(a);
    }
    __syncthreads();

    // ---- maxpool 2x2 s2: 4x4 -> 2x2, flatten ----
    if (tid < 64) {
        int f = tid >> 2, py = (tid >> 1) & 1, px = tid & 1;
        float m = sm[S_C2 + f * 16 + (2 * py) * 4 + (2 * px)];
        m = fmaxf(m, sm[S_C2 + f * 16 + (2 * py) * 4 + (2 * px + 1)]);
        m = fmaxf(m, sm[S_C2 + f * 16 + (2 * py + 1) * 4 + (2 * px)]);
        m = fmaxf(m, sm[S_C2 + f * 16 + (2 * py + 1) * 4 + (2 * px + 1)]);
        sm[S_FL + tid] = m;   // flat index == tid
    }
    __syncthreads();

    // ---- linear 64 -> 2 + sigmoid ----
    if (tid < 2) {
        float a = lb[tid];
        #pragma unroll
        for (int k = 0; k < 64; k++)
            a = fmaf(sm[S_FL + k], lw[tid * 64 + k], a);
        out[NBATCH * 20 + b * 2 + tid] = 1.f / (1.f + __expf(-a));
    }
}

extern "C" void kernel_launch(void* const* d_in, const int* in_sizes, int n_in,
                              void* d_out, int out_size)
{
    (void)in_sizes; (void)n_in; (void)out_size;
    const float* im = (const float*)d_in[0];
    // d_in[1] = x, d_in[2] = edge_index : dead (graph output is constant 0.05)
    const float* w1 = (const float*)d_in[3];
    const float* w2 = (const float*)d_in[4];
    const float* b2 = (const float*)d_in[5];
    const float* lw = (const float*)d_in[6];
    const float* lb = (const float*)d_in[7];
    float* out = (float*)d_out;

    cudaFuncSetAttribute(cnn_kernel, cudaFuncAttributeMaxDynamicSharedMemorySize,
                         SMEM_FLOATS * sizeof(float));
    cnn_kernel<<<NBATCH, 256, SMEM_FLOATS * sizeof(float)>>>(im, w1, w2, b2, lw, lb, out);
}